// round 5
// baseline (speedup 1.0000x reference)
#include <cuda_runtime.h>
#include <cuda_bf16.h>
#include <math.h>
#include <stdint.h>

#define BB 64
#define LL 1024
#define DD 256
#define TWO_D 512
#define HD 1280

typedef __nv_bfloat16 bf16;
typedef __nv_bfloat162 bf162;

// ---------------- scratch (device globals) ----------------
__device__ bf16 g_LIS[(size_t)BB * LL * TWO_D];      // [B*L][512] (qe|ce)
__device__ bf16 g_S[(size_t)BB * LL * LL];           // [B][L][L]
__device__ bf16 g_HRP[(size_t)BB * LL * TWO_D];
__device__ bf16 g_x[(size_t)BB * LL * DD];           // ping
__device__ bf16 g_x2[(size_t)BB * LL * DD];          // pong
__device__ bf16 g_cqc[(size_t)BB * LL * DD];
__device__ bf16 g_WmlpP[(size_t)TWO_D * HD];         // packed [pn=512][k=1280]
__device__ float g_bP[TWO_D];                        // packed mlp bias
__device__ bf16 g_convwP[(size_t)3 * TWO_D * 1024];  // packed [l][pn=512][k=1024]
__device__ float g_bconvP[3 * TWO_D];                // packed conv bias

__device__ __forceinline__ float sigmoidf_(float v) { return 1.f / (1.f + __expf(-v)); }

__device__ __forceinline__ float expp(float x) {
    float e = fmaf(x, 0.00833333f, 0.04166667f);
    e = fmaf(x, e, 0.16666667f);
    e = fmaf(x, e, 0.5f);
    e = fmaf(x, e, 1.0f);
    e = fmaf(x, e, 1.0f);
    if (x < -0.5f) e = __expf(x);
    return e;
}

// packed col mapping: pn -> original n
__device__ __host__ __forceinline__ int unpackN(int pn) {
    int hi = pn >> 8, c = pn & 255;
    return (c < 128) ? hi * 128 + c : 256 + hi * 128 + (c - 128);
}

// ---------------- async copy ----------------
__device__ __forceinline__ uint32_t s2u(const void* p) {
    return (uint32_t)__cvta_generic_to_shared(p);
}
__device__ __forceinline__ void cp16(char* dst, const void* src, bool v) {
    asm volatile("cp.async.cg.shared.global [%0], [%1], 16, %2;"
                 :: "r"(s2u(dst)), "l"(src), "r"(v ? 16 : 0));
}
#define CP_COMMIT() asm volatile("cp.async.commit_group;" ::: "memory")

// ---------------- mma ----------------
__device__ __forceinline__ void mma_bf16(float* c, const uint32_t* a, const uint32_t* b) {
    asm volatile(
        "mma.sync.aligned.m16n8k16.row.col.f32.bf16.bf16.f32 "
        "{%0,%1,%2,%3}, {%4,%5,%6,%7}, {%8,%9}, {%0,%1,%2,%3};"
        : "+f"(c[0]), "+f"(c[1]), "+f"(c[2]), "+f"(c[3])
        : "r"(a[0]), "r"(a[1]), "r"(a[2]), "r"(a[3]), "r"(b[0]), "r"(b[1]));
}

// ---------------- swizzles ----------------
__device__ __forceinline__ uint32_t swz128(uint32_t off) {
    return off ^ ((off >> 3) & 0x70);
}
// kn tiles with 512B rows: xor 16B-unit with row%8 inside each 128B sub-block
__device__ __forceinline__ uint32_t swzkn512(uint32_t row, uint32_t cb) {
    uint32_t unit = (cb >> 4) & 7;
    return row * 512 + (cb & 0x180) + (((unit ^ (row & 7)) << 4)) + (cb & 15);
}

// ---------------- smem layout: A 3x16KB, B 3x32KB ----------------
#define A_STAGE 16384
#define B_OFF   49152
#define B_STAGE 32768
#define SMEM_TOTAL 147456

// one K=64 chunk; CTA tile 128(M)x256(N); 16 warps (wm 4 x wn 4), warp tile 32x64
template <bool BT>
__device__ __forceinline__ void warp_k64(const char* As, const char* Bs,
                                         float acc[2][8][4], int wm, int wn, int lane) {
    uint32_t abase = s2u(As), bbase = s2u(Bs);
#pragma unroll
    for (int ks = 0; ks < 64; ks += 16) {
        uint32_t a[2][4];
#pragma unroll
        for (int t = 0; t < 2; t++) {
            uint32_t row = wm * 32 + t * 16 + ((lane >> 3) & 1) * 8 + (lane & 7);
            uint32_t cb = (ks + (lane >> 4) * 8) * 2;
            uint32_t ad = abase + swz128(row * 128 + cb);
            asm volatile("ldmatrix.sync.aligned.m8n8.x4.shared.b16 {%0,%1,%2,%3},[%4];"
                         : "=r"(a[t][0]), "=r"(a[t][1]), "=r"(a[t][2]), "=r"(a[t][3])
                         : "r"(ad));
        }
        uint32_t b[8][2];
#pragma unroll
        for (int p4 = 0; p4 < 4; p4++) {
            uint32_t r0, r1, r2, r3;
            if (BT) {
                uint32_t row = ks + ((lane >> 3) & 1) * 8 + (lane & 7);
                uint32_t cb = (wn * 64 + p4 * 16 + (lane >> 4) * 8) * 2;
                uint32_t ad = bbase + swzkn512(row, cb);
                asm volatile("ldmatrix.sync.aligned.m8n8.x4.trans.shared.b16 {%0,%1,%2,%3},[%4];"
                             : "=r"(r0), "=r"(r1), "=r"(r2), "=r"(r3) : "r"(ad));
            } else {
                uint32_t row = wn * 64 + p4 * 16 + (lane >> 4) * 8 + (lane & 7);
                uint32_t cb = (ks + ((lane >> 3) & 1) * 8) * 2;
                uint32_t ad = abase + swz128(row * 128 + cb);  // placeholder (unused)
                ad = bbase + swz128(row * 128 + cb);
                asm volatile("ldmatrix.sync.aligned.m8n8.x4.shared.b16 {%0,%1,%2,%3},[%4];"
                             : "=r"(r0), "=r"(r1), "=r"(r2), "=r"(r3) : "r"(ad));
            }
            b[2 * p4][0] = r0; b[2 * p4][1] = r1;
            b[2 * p4 + 1][0] = r2; b[2 * p4 + 1][1] = r3;
        }
#pragma unroll
        for (int t = 0; t < 2; t++)
#pragma unroll
            for (int j = 0; j < 8; j++)
                mma_bf16(acc[t][j], a[t], b[j]);
    }
}

// ---------------- stage loaders (512 threads) ----------------
// MODE 0=scores 1=hrp 2=mlp 3=conv
template <int MODE>
__device__ __forceinline__ void load_chunk(char* smem, int s, int k0, int tid,
                                           int bx, int by, int bz, int layer,
                                           const bf16* xsrc) {
    char* Ab = smem + s * A_STAGE;
    char* Bb = smem + B_OFF + s * B_STAGE;
    // ---- A: 128 rows x 128B ----
    {
        int row = tid >> 2, q = tid & 3;
        const bf16* src; bool v = true;
        if (MODE == 0) {
            src = g_LIS + ((size_t)(bz * LL + by * 128 + row) * TWO_D + k0);
        } else if (MODE == 1) {
            src = g_S + ((size_t)(bz * LL + by * 128 + row) * LL + k0);
        } else if (MODE == 2) {
            int r = by * 128 + row;
            if (k0 < 512)       src = g_LIS + ((size_t)r * TWO_D + k0);
            else if (k0 < 1024) src = g_HRP + ((size_t)r * TWO_D + (k0 - 512));
            else                src = g_cqc + ((size_t)r * DD + (k0 - 1024));
        } else {
            int ls = by * 128 + row + (k0 >> 8) - 3;
            v = (ls >= 0); if (!v) ls = 0;
            src = xsrc + ((size_t)(bz * LL + ls) * DD + (k0 & 255));
        }
#pragma unroll
        for (int j = 0; j < 2; j++) {
            uint32_t cb = q * 32 + j * 16;
            cp16(Ab + swz128((uint32_t)row * 128 + cb), src + cb / 2, v);
        }
    }
    // ---- B ----
    if (MODE == 1) {                    // kn512: 64 k-rows x 512B
        int row = tid >> 3, q = tid & 7;
        const bf16* src = g_LIS + ((size_t)(bz * LL + k0 + row) * TWO_D + bx * 256);
#pragma unroll
        for (int j = 0; j < 4; j++) {
            uint32_t cb = q * 64 + j * 16;
            cp16(Bb + swzkn512((uint32_t)row, cb), src + cb / 2, true);
        }
    } else {                            // mk: 256 n-rows x 128B
        int row = tid >> 1, h = tid & 1;
        const bf16* src;
        if (MODE == 0)      src = g_LIS + ((size_t)(bz * LL + bx * 256 + row) * TWO_D + k0);
        else if (MODE == 2) src = g_WmlpP + ((size_t)(bx * 256 + row) * HD + k0);
        else                src = g_convwP + ((size_t)(layer * TWO_D + bx * 256 + row) * 1024 + k0);
#pragma unroll
        for (int j = 0; j < 4; j++) {
            uint32_t cb = h * 64 + j * 16;
            cp16(Bb + swz128((uint32_t)row * 128 + cb), src + cb / 2, true);
        }
    }
}

template <int MODE>
__global__ void __launch_bounds__(512, 1) k_gemm(const bf16* __restrict__ xsrc,
                                                 bf16* __restrict__ xdst,
                                                 const float* __restrict__ biasP,
                                                 int layer) {
    extern __shared__ char smem[];
    int tid = threadIdx.x, wid = tid >> 5, lane = tid & 31;
    int bx = blockIdx.x, by = blockIdx.y, bz = blockIdx.z;
    if (MODE == 0 && bx * 256 > by * 128 + 127) return;
    int nch = (MODE == 0) ? 4 : (MODE == 1) ? (by + 1) * 2 : (MODE == 2) ? 20 : 16;
    int wm = wid >> 2, wn = wid & 3;

    float acc[2][8][4] = {};

    load_chunk<MODE>(smem, 0, 0, tid, bx, by, bz, layer, xsrc);  CP_COMMIT();
    load_chunk<MODE>(smem, 1, 64, tid, bx, by, bz, layer, xsrc); CP_COMMIT();

#pragma unroll 1
    for (int i = 0; i < nch; i++) {
        int s = i % 3;
        if (i == nch - 1) asm volatile("cp.async.wait_group 0;" ::: "memory");
        else              asm volatile("cp.async.wait_group 1;" ::: "memory");
        __syncthreads();
        if (i + 2 < nch) {
            load_chunk<MODE>(smem, (i + 2) % 3, (i + 2) * 64, tid, bx, by, bz, layer, xsrc);
            CP_COMMIT();
        }
        warp_k64<(MODE == 1)>(smem + s * A_STAGE, smem + B_OFF + s * B_STAGE,
                              acc, wm, wn, lane);
    }

    if (MODE == 0 || MODE == 1) {
        bf16* out; size_t ldc;
        if (MODE == 0) { out = g_S   + ((size_t)(bz * LL + by * 128)) * LL    + bx * 256; ldc = LL; }
        else           { out = g_HRP + ((size_t)(bz * LL + by * 128)) * TWO_D + bx * 256; ldc = TWO_D; }
#pragma unroll
        for (int t = 0; t < 2; t++)
#pragma unroll
            for (int j = 0; j < 8; j++) {
                int r = wm * 32 + t * 16 + (lane >> 2);
                int cc = wn * 64 + j * 8 + (lane & 3) * 2;
                float* a = acc[t][j];
                *(bf162*)(out + (size_t)r * ldc + cc) = __floats2bfloat162_rn(a[0], a[1]);
                *(bf162*)(out + (size_t)(r + 8) * ldc + cc) = __floats2bfloat162_rn(a[2], a[3]);
            }
        return;
    }

    // ---- GLU epilogue (MODE 2/3): stage f32 to smem, combine halves ----
    __syncthreads();
    float* sb = (float*)smem;           // [128][260]
    const float* bias = biasP + bx * 256;
#pragma unroll
    for (int t = 0; t < 2; t++)
#pragma unroll
        for (int j = 0; j < 8; j++) {
            int r = wm * 32 + t * 16 + (lane >> 2);
            int cc = wn * 64 + j * 8 + (lane & 3) * 2;
            float b0 = bias[cc], b1 = bias[cc + 1];
            float* a = acc[t][j];
            sb[r * 260 + cc]           = a[0] + b0;
            sb[r * 260 + cc + 1]       = a[1] + b1;
            sb[(r + 8) * 260 + cc]     = a[2] + b0;
            sb[(r + 8) * 260 + cc + 1] = a[3] + b1;
        }
    __syncthreads();
    {
        int row = tid >> 2, cbase = (tid & 3) * 32;
        size_t gr = (MODE == 2) ? (size_t)(by * 128 + row)
                                : ((size_t)bz * LL + by * 128 + row);
        bf16* orow = xdst + gr * DD + bx * 128 + cbase;
        const bf16* srow = (MODE == 3) ? (xsrc + gr * DD + bx * 128 + cbase) : nullptr;
        bf16 vals[32];
#pragma unroll
        for (int i = 0; i < 32; i++) {
            float a = sb[row * 260 + cbase + i];
            float g = sb[row * 260 + 128 + cbase + i];
            float v = a * sigmoidf_(g);
            if (MODE == 3) v += __bfloat162float(srow[i]);
            vals[i] = __float2bfloat16(v);
        }
#pragma unroll
        for (int qq = 0; qq < 4; qq++)
            ((uint4*)orow)[qq] = ((uint4*)vals)[qq];
    }
}

// ---------------- conversions / packing ----------------
__global__ void k_cvt_wmlpP(const float* __restrict__ W1w, const float* __restrict__ W2w) {
    int id = blockIdx.x * 256 + threadIdx.x;
    if (id >= TWO_D * HD) return;
    int pn = id / HD, k = id % HD;
    int n = unpackN(pn);
    float v = (n < DD) ? W1w[(size_t)n * HD + k] : W2w[(size_t)(n - DD) * HD + k];
    g_WmlpP[id] = __float2bfloat16(v);
}
__global__ void k_cvt_biasP(const float* __restrict__ b1, const float* __restrict__ b2,
                            const float* __restrict__ convb) {
    int pn = threadIdx.x;
    int n = unpackN(pn);
    g_bP[pn] = (n < DD) ? b1[n] : b2[n - DD];
    for (int l = 0; l < 3; l++)
        g_bconvP[l * TWO_D + pn] = convb[l * TWO_D + n];
}
__global__ __launch_bounds__(256) void k_cvt_convwP(const float* __restrict__ w) {
    __shared__ bf16 tile[64][72];
    int k0 = blockIdx.x * 64, n0 = blockIdx.y * 64, l = blockIdx.z;
    int row = threadIdx.x >> 2, seg = threadIdx.x & 3;
    const float* src = w + ((size_t)(l * 1024 + k0 + row)) * TWO_D + n0 + seg * 16;
#pragma unroll
    for (int j = 0; j < 16; j += 4) {
        float4 v = *(const float4*)(src + j);
        tile[row][seg * 16 + j]     = __float2bfloat16(v.x);
        tile[row][seg * 16 + j + 1] = __float2bfloat16(v.y);
        tile[row][seg * 16 + j + 2] = __float2bfloat16(v.z);
        tile[row][seg * 16 + j + 3] = __float2bfloat16(v.w);
    }
    __syncthreads();
    // packed dst row: n-tiles of 64 stay contiguous under packing
    int hi, c, n = n0;
    if (n < 256) { hi = n >> 7; c = n & 127; } else { hi = (n - 256) >> 7; c = 128 + ((n - 256) & 127); }
    int pn0 = hi * 256 + c;
    bf16* dst = g_convwP + ((size_t)(l * TWO_D + pn0 + row)) * 1024 + k0 + seg * 16;
    bf16 buf[16];
#pragma unroll
    for (int j = 0; j < 16; j++) buf[j] = tile[seg * 16 + j][row];
    *(uint4*)dst = *(uint4*)buf;
    *(uint4*)(dst + 8) = *(uint4*)(buf + 8);
}
__global__ void k_cvt_cqc(const float* __restrict__ cqc) {
    size_t id = (size_t)blockIdx.x * 256 + threadIdx.x;
    size_t n4 = (size_t)BB * LL * DD / 4;
    if (id >= n4) return;
    float4 v = ((const float4*)cqc)[id];
    bf162* o = (bf162*)g_cqc;
    o[id * 2] = __floats2bfloat162_rn(v.x, v.y);
    o[id * 2 + 1] = __floats2bfloat162_rn(v.z, v.w);
}
__global__ __launch_bounds__(256) void k_embed(const int* __restrict__ q,
                                               const int* __restrict__ c,
                                               const float* __restrict__ Eq,
                                               const float* __restrict__ Ec) {
    int r = blockIdx.x, d = threadIdx.x;
    int qi = q[r], ci = c[r];
    g_LIS[(size_t)r * TWO_D + d]      = __float2bfloat16(Eq[(size_t)qi * DD + d]);
    g_LIS[(size_t)r * TWO_D + DD + d] = __float2bfloat16(Ec[(size_t)ci * DD + d]);
}

// ---------------- softmax (templated per row-tile; only touches j < (BYT+1)*128) ----------------
template <int BYT>
__global__ __launch_bounds__(256) void k_softmax() {
    constexpr int NC = (BYT + 1) * 4;       // chunks of 32 cols
    int warp = threadIdx.x >> 5, lane = threadIdx.x & 31;
    int idx = blockIdx.x * 8 + warp;        // [0, 64*128)
    int b = idx >> 7, rowin = idx & 127;
    int i = BYT * 128 + rowin;
    bf16* row = g_S + ((size_t)b * LL + i) * LL;
    float e[NC];
    float m = -3.0e38f;
#pragma unroll
    for (int c = 0; c < NC; c++) {
        int j = c * 32 + lane;
        float v = (j <= i) ? __bfloat162float(row[j]) : -3.0e38f;
        e[c] = v;
        m = fmaxf(m, v);
    }
#pragma unroll
    for (int off = 16; off > 0; off >>= 1)
        m = fmaxf(m, __shfl_xor_sync(0xffffffffu, m, off));
    float ssum = 0.f, pii = 0.f;
#pragma unroll
    for (int c = 0; c < NC; c++) {
        int j = c * 32 + lane;
        float ev = (j <= i) ? expp(e[c] - m) : 0.f;
        e[c] = ev;
        ssum += ev;
        if (j == i) pii = ev;
    }
#pragma unroll
    for (int off = 16; off > 0; off >>= 1) {
        ssum += __shfl_xor_sync(0xffffffffu, ssum, off);
        pii += __shfl_xor_sync(0xffffffffu, pii, off);
    }
    float inv = 1.f / ((ssum - pii) + 1e-8f * ssum);
#pragma unroll
    for (int c = 0; c < NC; c++) {
        int j = c * 32 + lane;
        row[j] = __float2bfloat16((j < i) ? e[c] * inv : 0.f);
    }
}

// ---------------- predict ----------------
__global__ __launch_bounds__(256) void k_predict(const bf16* __restrict__ xf,
                                                 float* __restrict__ out) {
    int warp = threadIdx.x >> 5, lane = threadIdx.x & 31;
    int o = blockIdx.x * 8 + warp;
    if (o >= BB * (LL - 1)) return;
    int b = o / (LL - 1), l = o % (LL - 1);
    const bf16* xr = xf + (size_t)(b * LL + l) * DD;
    const bf16* qr = g_LIS + (size_t)(b * LL + l + 1) * TWO_D;
    float s = 0.f;
    for (int d = lane; d < DD; d += 32)
        s += __bfloat162float(xr[d]) * __bfloat162float(qr[d]);
#pragma unroll
    for (int off = 16; off > 0; off >>= 1) s += __shfl_down_sync(0xffffffffu, s, off);
    if (lane == 0) out[o] = sigmoidf_(s);
}

// device-symbol address helpers
static bf16* addr_of_x() { void* p; cudaGetSymbolAddress(&p, g_x); return (bf16*)p; }
static bf16* addr_of_x2() { void* p; cudaGetSymbolAddress(&p, g_x2); return (bf16*)p; }
static float* addr_of_bP() { void* p; cudaGetSymbolAddress(&p, g_bP); return (float*)p; }
static float* addr_of_bconvP() { void* p; cudaGetSymbolAddress(&p, g_bconvP); return (float*)p; }

// ---------------- launch ----------------
extern "C" void kernel_launch(void* const* d_in, const int* in_sizes, int n_in,
                              void* d_out, int out_size) {
    (void)in_sizes; (void)n_in; (void)out_size;
    const int*   q     = (const int*)d_in[0];
    const int*   c     = (const int*)d_in[1];
    const float* cqc   = (const float*)d_in[2];
    const float* Eq    = (const float*)d_in[3];
    const float* Ec    = (const float*)d_in[4];
    const float* W1w   = (const float*)d_in[5];
    const float* W1b   = (const float*)d_in[6];
    const float* W2w   = (const float*)d_in[7];
    const float* W2b   = (const float*)d_in[8];
    const float* convw = (const float*)d_in[9];
    const float* convb = (const float*)d_in[10];
    float* out = (float*)d_out;

    static bf16 *xA = nullptr, *xB = nullptr;
    static float *bP = nullptr, *bconvP = nullptr;
    static bool init_done = false;
    if (!init_done) {
        cudaFuncSetAttribute(k_gemm<0>, cudaFuncAttributeMaxDynamicSharedMemorySize, SMEM_TOTAL);
        cudaFuncSetAttribute(k_gemm<1>, cudaFuncAttributeMaxDynamicSharedMemorySize, SMEM_TOTAL);
        cudaFuncSetAttribute(k_gemm<2>, cudaFuncAttributeMaxDynamicSharedMemorySize, SMEM_TOTAL);
        cudaFuncSetAttribute(k_gemm<3>, cudaFuncAttributeMaxDynamicSharedMemorySize, SMEM_TOTAL);
        xA = addr_of_x(); xB = addr_of_x2();
        bP = addr_of_bP(); bconvP = addr_of_bconvP();
        init_done = true;
    }

    k_cvt_wmlpP<<<(TWO_D * HD + 255) / 256, 256>>>(W1w, W2w);
    k_cvt_biasP<<<1, 512>>>(W1b, W2b, convb);
    k_cvt_convwP<<<dim3(16, 8, 3), 256>>>(convw);
    k_cvt_cqc<<<(BB * LL * DD / 4 + 255) / 256, 256>>>(cqc);
    k_embed<<<BB * LL, 256>>>(q, c, Eq, Ec);

    // scores
    k_gemm<0><<<dim3(4, 8, BB), 512, SMEM_TOTAL>>>(nullptr, nullptr, nullptr, 0);
    // softmax per row-tile
    k_softmax<0><<<1024, 256>>>();
    k_softmax<1><<<1024, 256>>>();
    k_softmax<2><<<1024, 256>>>();
    k_softmax<3><<<1024, 256>>>();
    k_softmax<4><<<1024, 256>>>();
    k_softmax<5><<<1024, 256>>>();
    k_softmax<6><<<1024, 256>>>();
    k_softmax<7><<<1024, 256>>>();
    // hrp
    k_gemm<1><<<dim3(2, 8, BB), 512, SMEM_TOTAL>>>(nullptr, nullptr, nullptr, 0);
    // mlp + fused GLU -> xA
    k_gemm<2><<<dim3(2, 512, 1), 512, SMEM_TOTAL>>>(nullptr, xA, bP, 0);
    // conv stack, ping-pong
    bf16* src = xA;
    bf16* dst = xB;
    for (int l = 0; l < 3; l++) {
        k_gemm<3><<<dim3(2, 8, BB), 512, SMEM_TOTAL>>>(src, dst, bconvP + l * TWO_D, l);
        bf16* t = src; src = dst; dst = t;
    }
    // final activation is in src after swap (l=2 wrote xB)
    k_predict<<<(BB * (LL - 1) + 7) / 8, 256>>>(src, out);
}

// round 6
// speedup vs baseline: 1.5979x; 1.5979x over previous
#include <cuda_runtime.h>
#include <cuda_bf16.h>
#include <math.h>
#include <stdint.h>

#define BB 64
#define LL 1024
#define DD 256
#define TWO_D 512
#define HD 1280

typedef __nv_bfloat16 bf16;
typedef __nv_bfloat162 bf162;

// ---------------- scratch (device globals) ----------------
__device__ bf16 g_LIS[(size_t)BB * LL * TWO_D];      // [B*L][512] (qe|ce)
__device__ bf16 g_S[(size_t)BB * LL * LL];           // [B][L][L]
__device__ bf16 g_HRP[(size_t)BB * LL * TWO_D];
__device__ bf16 g_x[(size_t)BB * LL * DD];           // ping
__device__ bf16 g_x2[(size_t)BB * LL * DD];          // pong
__device__ bf16 g_cqc[(size_t)BB * LL * DD];
__device__ bf16 g_WmlpP[(size_t)TWO_D * HD];         // packed [pn=512][k=1280]
__device__ float g_bP[TWO_D];                        // packed mlp bias
__device__ bf16 g_convwP[(size_t)3 * TWO_D * 1024];  // packed [l][pn=512][k=1024]
__device__ float g_bconvP[3 * TWO_D];                // packed conv bias

__device__ __forceinline__ float sigmoidf_(float v) { return 1.f / (1.f + __expf(-v)); }

__device__ __forceinline__ float expp(float x) {
    float e = fmaf(x, 0.00833333f, 0.04166667f);
    e = fmaf(x, e, 0.16666667f);
    e = fmaf(x, e, 0.5f);
    e = fmaf(x, e, 1.0f);
    e = fmaf(x, e, 1.0f);
    if (x < -0.5f) e = __expf(x);
    return e;
}

// packed col mapping: pn = 64*s + c; c<32 -> a-col s*32+c ; else gate-col 256+s*32+(c-32)
__device__ __forceinline__ int unpackN64(int pn) {
    int s = pn >> 6, c = pn & 63;
    return (c < 32) ? s * 32 + c : 256 + s * 32 + (c - 32);
}

// ---------------- async copy ----------------
__device__ __forceinline__ uint32_t s2u(const void* p) {
    return (uint32_t)__cvta_generic_to_shared(p);
}
__device__ __forceinline__ void cp16(char* dst, const void* src, bool v) {
    asm volatile("cp.async.cg.shared.global [%0], [%1], 16, %2;"
                 :: "r"(s2u(dst)), "l"(src), "r"(v ? 16 : 0));
}
#define CP_COMMIT() asm volatile("cp.async.commit_group;" ::: "memory")

// ---------------- mma ----------------
__device__ __forceinline__ void mma_bf16(float* c, const uint32_t* a, const uint32_t* b) {
    asm volatile(
        "mma.sync.aligned.m16n8k16.row.col.f32.bf16.bf16.f32 "
        "{%0,%1,%2,%3}, {%4,%5,%6,%7}, {%8,%9}, {%0,%1,%2,%3};"
        : "+f"(c[0]), "+f"(c[1]), "+f"(c[2]), "+f"(c[3])
        : "r"(a[0]), "r"(a[1]), "r"(a[2]), "r"(a[3]), "r"(b[0]), "r"(b[1]));
}

// ---------------- swizzles ----------------
__device__ __forceinline__ uint32_t swz128(uint32_t off) {
    return off ^ ((off >> 3) & 0x70);
}
// kn tiles: rows of 256B (128 bf16): unit ^= row%8 within each 128B half.
__device__ __forceinline__ uint32_t swzkn(uint32_t row, uint32_t cb) {
    uint32_t unit = (cb >> 4) & 7;
    return row * 256 + (cb & 0x80) + ((unit ^ (row & 7)) << 4) + (cb & 15);
}

// ---------------- compute one K=64 chunk (128x128 CTA tile, 8 warps 4x2) ----------------
template <bool BT>
__device__ __forceinline__ void warp_k64(const char* As, const char* Bs,
                                         float acc[16][4], int wm, int wn, int lane) {
    uint32_t abase = s2u(As), bbase = s2u(Bs);
#pragma unroll
    for (int ks = 0; ks < 64; ks += 16) {
        uint32_t a[2][4];
#pragma unroll
        for (int t = 0; t < 2; t++) {
            uint32_t row = wm * 32 + t * 16 + ((lane >> 3) & 1) * 8 + (lane & 7);
            uint32_t cb = (ks + (lane >> 4) * 8) * 2;
            uint32_t ad = abase + swz128(row * 128 + cb);
            asm volatile("ldmatrix.sync.aligned.m8n8.x4.shared.b16 {%0,%1,%2,%3},[%4];"
                         : "=r"(a[t][0]), "=r"(a[t][1]), "=r"(a[t][2]), "=r"(a[t][3])
                         : "r"(ad));
        }
        uint32_t b[8][2];
#pragma unroll
        for (int p4 = 0; p4 < 4; p4++) {
            uint32_t r0, r1, r2, r3;
            if (BT) {
                uint32_t row = ks + ((lane >> 3) & 1) * 8 + (lane & 7);
                uint32_t cb = (wn * 64 + p4 * 16 + (lane >> 4) * 8) * 2;
                uint32_t ad = bbase + swzkn(row, cb);
                asm volatile("ldmatrix.sync.aligned.m8n8.x4.trans.shared.b16 {%0,%1,%2,%3},[%4];"
                             : "=r"(r0), "=r"(r1), "=r"(r2), "=r"(r3) : "r"(ad));
            } else {
                uint32_t row = wn * 64 + p4 * 16 + (lane >> 4) * 8 + (lane & 7);
                uint32_t cb = (ks + ((lane >> 3) & 1) * 8) * 2;
                uint32_t ad = bbase + swz128(row * 128 + cb);
                asm volatile("ldmatrix.sync.aligned.m8n8.x4.shared.b16 {%0,%1,%2,%3},[%4];"
                             : "=r"(r0), "=r"(r1), "=r"(r2), "=r"(r3) : "r"(ad));
            }
            b[2 * p4][0] = r0; b[2 * p4][1] = r1;
            b[2 * p4 + 1][0] = r2; b[2 * p4 + 1][1] = r3;
        }
#pragma unroll
        for (int t = 0; t < 2; t++)
#pragma unroll
            for (int j = 0; j < 8; j++)
                mma_bf16(acc[t * 8 + j], a[t], b[j]);
    }
}

// ---------------- pipelined GEMM kernel ----------------
// MODE 0=scores 1=hrp 2=mlp(+GLU) 3=conv(+GLU+res).  128x128 tiles, K64, 3 stages.
#define STAGE_BYTES 16384
#define B_SMEM_OFF  (3 * 16384)
#define SMEM_TOTAL  (6 * 16384)

template <int MODE>
__device__ __forceinline__ void load_chunk(char* smem, int s, int k0, int tid,
                                           int bx, int by, int bz, int layer,
                                           const bf16* xsrc) {
    char* Ab = smem + s * STAGE_BYTES;
    char* Bb = smem + B_SMEM_OFF + s * STAGE_BYTES;
    // ---- A: 128 rows x 64 els ----
    {
        int row = tid >> 1, h = tid & 1;
        const bf16* src; bool v = true;
        if (MODE == 0) {
            src = g_LIS + ((size_t)(bz * LL + by * 128 + row) * TWO_D + k0);
        } else if (MODE == 1) {
            src = g_S + ((size_t)(bz * LL + by * 128 + row) * LL + k0);
        } else if (MODE == 2) {
            int r = by * 128 + row;
            if (k0 < 512)       src = g_LIS + ((size_t)r * TWO_D + k0);
            else if (k0 < 1024) src = g_HRP + ((size_t)r * TWO_D + (k0 - 512));
            else                src = g_cqc + ((size_t)r * DD + (k0 - 1024));
        } else {
            int ls = by * 128 + row + (k0 >> 8) - 3;
            v = (ls >= 0); if (!v) ls = 0;
            src = xsrc + ((size_t)(bz * LL + ls) * DD + (k0 & 255));
        }
#pragma unroll
        for (int j = 0; j < 4; j++) {
            uint32_t cb = h * 64 + j * 16;
            cp16(Ab + swz128((uint32_t)row * 128 + cb), src + cb / 2, v);
        }
    }
    // ---- B ----
    if (MODE == 1) {                    // kn layout: 64 k-rows x 128 els (trans)
        int row = tid >> 2, q = tid & 3;
        const bf16* src = g_LIS + ((size_t)(bz * LL + k0 + row) * TWO_D + bx * 128);
#pragma unroll
        for (int j = 0; j < 4; j++) {
            uint32_t cb = q * 64 + j * 16;
            cp16(Bb + swzkn((uint32_t)row, cb), src + cb / 2, true);
        }
    } else {                            // mk layout: 128 n-rows x 64 els
        int row = tid >> 1, h = tid & 1;
        const bf16* src;
        if (MODE == 0)      src = g_LIS + ((size_t)(bz * LL + bx * 128 + row) * TWO_D + k0);
        else if (MODE == 2) src = g_WmlpP + ((size_t)(bx * 128 + row) * HD + k0);
        else                src = g_convwP + ((size_t)(layer * TWO_D + bx * 128 + row)) * 1024 + k0;
#pragma unroll
        for (int j = 0; j < 4; j++) {
            uint32_t cb = h * 64 + j * 16;
            cp16(Bb + swz128((uint32_t)row * 128 + cb), src + cb / 2, true);
        }
    }
}

template <int MODE>
__global__ void __launch_bounds__(256, 2) k_gemm(const bf16* __restrict__ xsrc,
                                                 bf16* __restrict__ xdst,
                                                 const float* __restrict__ biasP,
                                                 int layer) {
    extern __shared__ char smem[];
    int tid = threadIdx.x, wid = tid >> 5, lane = tid & 31;
    int bx = blockIdx.x, by = blockIdx.y, bz = blockIdx.z;
    if (MODE == 0 && bx > by) return;
    int nch = (MODE == 0) ? 4 : (MODE == 1) ? (by + 1) * 2 : (MODE == 2) ? 20 : 16;
    int wm = wid >> 1, wn = wid & 1;

    float acc[16][4] = {};

    load_chunk<MODE>(smem, 0, 0, tid, bx, by, bz, layer, xsrc);  CP_COMMIT();
    load_chunk<MODE>(smem, 1, 64, tid, bx, by, bz, layer, xsrc); CP_COMMIT();

#pragma unroll 1
    for (int i = 0; i < nch; i++) {
        int s = i % 3;
        if (i == nch - 1) asm volatile("cp.async.wait_group 0;" ::: "memory");
        else              asm volatile("cp.async.wait_group 1;" ::: "memory");
        __syncthreads();
        if (i + 2 < nch) {
            load_chunk<MODE>(smem, (i + 2) % 3, (i + 2) * 64, tid, bx, by, bz, layer, xsrc);
            CP_COMMIT();
        }
        warp_k64<(MODE == 1)>(smem + s * STAGE_BYTES, smem + B_SMEM_OFF + s * STAGE_BYTES,
                              acc, wm, wn, lane);
    }

    if (MODE == 0 || MODE == 1) {
        bf16* out; size_t ldc;
        if (MODE == 0) { out = g_S   + ((size_t)(bz * LL + by * 128)) * LL    + bx * 128; ldc = LL; }
        else           { out = g_HRP + ((size_t)(bz * LL + by * 128)) * TWO_D + bx * 128; ldc = TWO_D; }
#pragma unroll
        for (int t = 0; t < 2; t++)
#pragma unroll
            for (int j = 0; j < 8; j++) {
                int r = wm * 32 + t * 16 + (lane >> 2);
                int cc = wn * 64 + j * 8 + (lane & 3) * 2;
                float* a = acc[t * 8 + j];
                *(bf162*)(out + (size_t)r * ldc + cc) = __floats2bfloat162_rn(a[0], a[1]);
                *(bf162*)(out + (size_t)(r + 8) * ldc + cc) = __floats2bfloat162_rn(a[2], a[3]);
            }
    } else {
        // ---- register-resident GLU epilogue ----
        // thread holds a-cols in acc[t*8+j] (j 0..3) and matching gates in acc[t*8+j+4].
#pragma unroll
        for (int t = 0; t < 2; t++)
#pragma unroll
            for (int j = 0; j < 4; j++) {
                int r = wm * 32 + t * 16 + (lane >> 2);
                int pc = wn * 64 + j * 8 + (lane & 3) * 2;          // packed a-col in tile
                float ba0 = biasP[bx * 128 + pc],      ba1 = biasP[bx * 128 + pc + 1];
                float bg0 = biasP[bx * 128 + pc + 32], bg1 = biasP[bx * 128 + pc + 33];
                float* a = acc[t * 8 + j];
                float* g = acc[t * 8 + j + 4];
                int ocol = (bx * 2 + wn) * 32 + j * 8 + (lane & 3) * 2;
                size_t gr0 = (MODE == 2) ? (size_t)(by * 128 + r)
                                         : ((size_t)bz * LL + by * 128 + r);
                float v0 = (a[0] + ba0) * sigmoidf_(g[0] + bg0);
                float v1 = (a[1] + ba1) * sigmoidf_(g[1] + bg1);
                float v2 = (a[2] + ba0) * sigmoidf_(g[2] + bg0);
                float v3 = (a[3] + ba1) * sigmoidf_(g[3] + bg1);
                if (MODE == 3) {
                    bf162 r0 = *(const bf162*)(xsrc + gr0 * DD + ocol);
                    bf162 r1 = *(const bf162*)(xsrc + (gr0 + 8) * DD + ocol);
                    v0 += __bfloat162float(r0.x); v1 += __bfloat162float(r0.y);
                    v2 += __bfloat162float(r1.x); v3 += __bfloat162float(r1.y);
                }
                *(bf162*)(xdst + gr0 * DD + ocol)       = __floats2bfloat162_rn(v0, v1);
                *(bf162*)(xdst + (gr0 + 8) * DD + ocol) = __floats2bfloat162_rn(v2, v3);
            }
    }
}

// ---------------- conversions / packing ----------------
__global__ void k_cvt_wmlpP(const float* __restrict__ W1w, const float* __restrict__ W2w) {
    int id = blockIdx.x * 256 + threadIdx.x;
    if (id >= TWO_D * HD) return;
    int pn = id / HD, k = id % HD;
    int n = unpackN64(pn);
    float v = (n < DD) ? W1w[(size_t)n * HD + k] : W2w[(size_t)(n - DD) * HD + k];
    g_WmlpP[id] = __float2bfloat16(v);
}
__global__ void k_cvt_biasP(const float* __restrict__ b1, const float* __restrict__ b2,
                            const float* __restrict__ convb) {
    int pn = threadIdx.x;
    int n = unpackN64(pn);
    g_bP[pn] = (n < DD) ? b1[n] : b2[n - DD];
    for (int l = 0; l < 3; l++)
        g_bconvP[l * TWO_D + pn] = convb[l * TWO_D + n];
}
// conv weights: [l][k=1024][n=512] -> packed transposed [l][pn=512][k=1024]
// block: 64 k x 32 n tile
__global__ __launch_bounds__(256) void k_cvt_convwP(const float* __restrict__ w) {
    __shared__ bf16 tile[64][40];
    int k0 = blockIdx.x * 64, n0 = blockIdx.y * 32, l = blockIdx.z;
    {
        int row = threadIdx.x >> 2, seg = threadIdx.x & 3;   // 64 rows x 4 segs of 8
        const float* src = w + ((size_t)(l * 1024 + k0 + row)) * TWO_D + n0 + seg * 8;
        float4 v0 = *(const float4*)src;
        float4 v1 = *(const float4*)(src + 4);
        tile[row][seg * 8 + 0] = __float2bfloat16(v0.x);
        tile[row][seg * 8 + 1] = __float2bfloat16(v0.y);
        tile[row][seg * 8 + 2] = __float2bfloat16(v0.z);
        tile[row][seg * 8 + 3] = __float2bfloat16(v0.w);
        tile[row][seg * 8 + 4] = __float2bfloat16(v1.x);
        tile[row][seg * 8 + 5] = __float2bfloat16(v1.y);
        tile[row][seg * 8 + 6] = __float2bfloat16(v1.z);
        tile[row][seg * 8 + 7] = __float2bfloat16(v1.w);
    }
    __syncthreads();
    {
        int s = (n0 < 256) ? (n0 >> 5) : ((n0 - 256) >> 5);
        int pn0 = s * 64 + ((n0 < 256) ? 0 : 32);
        int row = threadIdx.x >> 3, seg = threadIdx.x & 7;   // 32 pn-rows x 8 segs of 8
        bf16 buf[8];
#pragma unroll
        for (int j = 0; j < 8; j++) buf[j] = tile[seg * 8 + j][row];
        bf16* dst = g_convwP + ((size_t)(l * TWO_D + pn0 + row)) * 1024 + k0 + seg * 8;
        *(uint4*)dst = *(uint4*)buf;
    }
}
__global__ void k_cvt_cqc(const float* __restrict__ cqc) {
    size_t id = (size_t)blockIdx.x * 256 + threadIdx.x;
    size_t n4 = (size_t)BB * LL * DD / 4;
    if (id >= n4) return;
    float4 v = ((const float4*)cqc)[id];
    bf162* o = (bf162*)g_cqc;
    o[id * 2] = __floats2bfloat162_rn(v.x, v.y);
    o[id * 2 + 1] = __floats2bfloat162_rn(v.z, v.w);
}
__global__ __launch_bounds__(256) void k_embed(const int* __restrict__ q,
                                               const int* __restrict__ c,
                                               const float* __restrict__ Eq,
                                               const float* __restrict__ Ec) {
    int r = blockIdx.x, d = threadIdx.x;
    int qi = q[r], ci = c[r];
    g_LIS[(size_t)r * TWO_D + d]      = __float2bfloat16(Eq[(size_t)qi * DD + d]);
    g_LIS[(size_t)r * TWO_D + DD + d] = __float2bfloat16(Ec[(size_t)ci * DD + d]);
}

// ---------------- triangular softmax (per row-tile template) ----------------
template <int BYT>
__global__ __launch_bounds__(256) void k_softmax() {
    constexpr int NC = (BYT + 1) * 4;
    int warp = threadIdx.x >> 5, lane = threadIdx.x & 31;
    int idx = blockIdx.x * 8 + warp;
    int b = idx >> 7, rowin = idx & 127;
    int i = BYT * 128 + rowin;
    bf16* row = g_S + ((size_t)b * LL + i) * LL;
    float e[NC];
    float m = -3.0e38f;
#pragma unroll
    for (int c = 0; c < NC; c++) {
        int j = c * 32 + lane;
        float v = (j <= i) ? __bfloat162float(row[j]) : -3.0e38f;
        e[c] = v;
        m = fmaxf(m, v);
    }
#pragma unroll
    for (int off = 16; off > 0; off >>= 1)
        m = fmaxf(m, __shfl_xor_sync(0xffffffffu, m, off));
    float ssum = 0.f, pii = 0.f;
#pragma unroll
    for (int c = 0; c < NC; c++) {
        int j = c * 32 + lane;
        float ev = (j <= i) ? expp(e[c] - m) : 0.f;
        e[c] = ev;
        ssum += ev;
        if (j == i) pii = ev;
    }
#pragma unroll
    for (int off = 16; off > 0; off >>= 1) {
        ssum += __shfl_xor_sync(0xffffffffu, ssum, off);
        pii += __shfl_xor_sync(0xffffffffu, pii, off);
    }
    float inv = 1.f / ((ssum - pii) + 1e-8f * ssum);
#pragma unroll
    for (int c = 0; c < NC; c++) {
        int j = c * 32 + lane;
        row[j] = __float2bfloat16((j < i) ? e[c] * inv : 0.f);
    }
}

// ---------------- predict ----------------
__global__ __launch_bounds__(256) void k_predict(const bf16* __restrict__ xf,
                                                 float* __restrict__ out) {
    int warp = threadIdx.x >> 5, lane = threadIdx.x & 31;
    int o = blockIdx.x * 8 + warp;
    if (o >= BB * (LL - 1)) return;
    int b = o / (LL - 1), l = o % (LL - 1);
    const bf16* xr = xf + (size_t)(b * LL + l) * DD;
    const bf16* qr = g_LIS + (size_t)(b * LL + l + 1) * TWO_D;
    float s = 0.f;
    for (int d = lane; d < DD; d += 32)
        s += __bfloat162float(xr[d]) * __bfloat162float(qr[d]);
#pragma unroll
    for (int off = 16; off > 0; off >>= 1) s += __shfl_down_sync(0xffffffffu, s, off);
    if (lane == 0) out[o] = sigmoidf_(s);
}

static bf16* addr_x() { void* p; cudaGetSymbolAddress(&p, g_x); return (bf16*)p; }
static bf16* addr_x2() { void* p; cudaGetSymbolAddress(&p, g_x2); return (bf16*)p; }
static float* addr_bP() { void* p; cudaGetSymbolAddress(&p, g_bP); return (float*)p; }
static float* addr_bconvP() { void* p; cudaGetSymbolAddress(&p, g_bconvP); return (float*)p; }

// ---------------- launch ----------------
extern "C" void kernel_launch(void* const* d_in, const int* in_sizes, int n_in,
                              void* d_out, int out_size) {
    (void)in_sizes; (void)n_in; (void)out_size;
    const int*   q     = (const int*)d_in[0];
    const int*   c     = (const int*)d_in[1];
    const float* cqc   = (const float*)d_in[2];
    const float* Eq    = (const float*)d_in[3];
    const float* Ec    = (const float*)d_in[4];
    const float* W1w   = (const float*)d_in[5];
    const float* W1b   = (const float*)d_in[6];
    const float* W2w   = (const float*)d_in[7];
    const float* W2b   = (const float*)d_in[8];
    const float* convw = (const float*)d_in[9];
    const float* convb = (const float*)d_in[10];
    float* out = (float*)d_out;

    static bf16 *xA = nullptr, *xB = nullptr;
    static float *bP = nullptr, *bconvP = nullptr;
    static bool init_done = false;
    if (!init_done) {
        cudaFuncSetAttribute(k_gemm<0>, cudaFuncAttributeMaxDynamicSharedMemorySize, SMEM_TOTAL);
        cudaFuncSetAttribute(k_gemm<1>, cudaFuncAttributeMaxDynamicSharedMemorySize, SMEM_TOTAL);
        cudaFuncSetAttribute(k_gemm<2>, cudaFuncAttributeMaxDynamicSharedMemorySize, SMEM_TOTAL);
        cudaFuncSetAttribute(k_gemm<3>, cudaFuncAttributeMaxDynamicSharedMemorySize, SMEM_TOTAL);
        xA = addr_x(); xB = addr_x2();
        bP = addr_bP(); bconvP = addr_bconvP();
        init_done = true;
    }

    k_cvt_wmlpP<<<(TWO_D * HD + 255) / 256, 256>>>(W1w, W2w);
    k_cvt_biasP<<<1, 512>>>(W1b, W2b, convb);
    k_cvt_convwP<<<dim3(16, 16, 3), 256>>>(convw);
    k_cvt_cqc<<<(BB * LL * DD / 4 + 255) / 256, 256>>>(cqc);
    k_embed<<<BB * LL, 256>>>(q, c, Eq, Ec);

    k_gemm<0><<<dim3(8, 8, BB), 256, SMEM_TOTAL>>>(nullptr, nullptr, nullptr, 0);
    k_softmax<0><<<1024, 256>>>();
    k_softmax<1><<<1024, 256>>>();
    k_softmax<2><<<1024, 256>>>();
    k_softmax<3><<<1024, 256>>>();
    k_softmax<4><<<1024, 256>>>();
    k_softmax<5><<<1024, 256>>>();
    k_softmax<6><<<1024, 256>>>();
    k_softmax<7><<<1024, 256>>>();
    k_gemm<1><<<dim3(4, 8, BB), 256, SMEM_TOTAL>>>(nullptr, nullptr, nullptr, 0);
    k_gemm<2><<<dim3(4, 512, 1), 256, SMEM_TOTAL>>>(nullptr, xA, bP, 0);
    bf16* src = xA;
    bf16* dst = xB;
    for (int l = 0; l < 3; l++) {
        k_gemm<3><<<dim3(4, 8, BB), 256, SMEM_TOTAL>>>(src, dst, bconvP + l * TWO_D, l);
        bf16* t = src; src = dst; dst = t;
    }
    k_predict<<<(BB * (LL - 1) + 7) / 8, 256>>>(src, out);
}

// round 7
// speedup vs baseline: 1.6364x; 1.0241x over previous
#include <cuda_runtime.h>
#include <cuda_bf16.h>
#include <math.h>
#include <stdint.h>

#define BB 64
#define LL 1024
#define DD 256
#define TWO_D 512
#define HD 1280

typedef __nv_bfloat16 bf16;
typedef __nv_bfloat162 bf162;

// ---------------- scratch (device globals) ----------------
__device__ bf16 g_LIS[(size_t)BB * LL * TWO_D];      // [B*L][512] (qe|ce)
__device__ bf16 g_S[(size_t)BB * LL * LL];           // [B][L][L] holds exp'd causal P
__device__ bf16 g_HRP[(size_t)BB * LL * TWO_D];
__device__ bf16 g_x[(size_t)BB * LL * DD];           // ping
__device__ bf16 g_x2[(size_t)BB * LL * DD];          // pong
__device__ bf16 g_cqc[(size_t)BB * LL * DD];
__device__ bf16 g_WmlpP[(size_t)TWO_D * HD];         // packed [pn=512][k=1280]
__device__ float g_bP[TWO_D];                        // packed mlp bias
__device__ bf16 g_convwP[(size_t)3 * TWO_D * 1024];  // packed [l][pn=512][k=1024]
__device__ float g_bconvP[3 * TWO_D];                // packed conv bias
__device__ float g_rowsum[(size_t)BB * LL];          // sum_{j<i} e^{s_ij}
__device__ float g_pii[(size_t)BB * LL];             // e^{s_ii}

__device__ __forceinline__ float sigmoidf_(float v) { return 1.f / (1.f + __expf(-v)); }

__device__ __forceinline__ float expp(float x) {
    float e = fmaf(x, 0.00833333f, 0.04166667f);
    e = fmaf(x, e, 0.16666667f);
    e = fmaf(x, e, 0.5f);
    e = fmaf(x, e, 1.0f);
    e = fmaf(x, e, 1.0f);
    if (fabsf(x) > 0.5f) e = __expf(x);
    return e;
}

// packed col mapping: pn = 64*s + c; c<32 -> a-col s*32+c ; else gate-col 256+s*32+(c-32)
__device__ __forceinline__ int unpackN64(int pn) {
    int s = pn >> 6, c = pn & 63;
    return (c < 32) ? s * 32 + c : 256 + s * 32 + (c - 32);
}

// ---------------- async copy ----------------
__device__ __forceinline__ uint32_t s2u(const void* p) {
    return (uint32_t)__cvta_generic_to_shared(p);
}
__device__ __forceinline__ void cp16(char* dst, const void* src, bool v) {
    asm volatile("cp.async.cg.shared.global [%0], [%1], 16, %2;"
                 :: "r"(s2u(dst)), "l"(src), "r"(v ? 16 : 0));
}
#define CP_COMMIT() asm volatile("cp.async.commit_group;" ::: "memory")

// ---------------- mma ----------------
__device__ __forceinline__ void mma_bf16(float* c, const uint32_t* a, const uint32_t* b) {
    asm volatile(
        "mma.sync.aligned.m16n8k16.row.col.f32.bf16.bf16.f32 "
        "{%0,%1,%2,%3}, {%4,%5,%6,%7}, {%8,%9}, {%0,%1,%2,%3};"
        : "+f"(c[0]), "+f"(c[1]), "+f"(c[2]), "+f"(c[3])
        : "r"(a[0]), "r"(a[1]), "r"(a[2]), "r"(a[3]), "r"(b[0]), "r"(b[1]));
}

// ---------------- swizzles ----------------
__device__ __forceinline__ uint32_t swz128(uint32_t off) {
    return off ^ ((off >> 3) & 0x70);
}
__device__ __forceinline__ uint32_t swzkn(uint32_t row, uint32_t cb) {
    uint32_t unit = (cb >> 4) & 7;
    return row * 256 + (cb & 0x80) + ((unit ^ (row & 7)) << 4) + (cb & 15);
}

// ---------------- compute one K=64 chunk (128x128 CTA tile, 8 warps 4x2) ----------------
template <bool BT>
__device__ __forceinline__ void warp_k64(const char* As, const char* Bs,
                                         float acc[16][4], int wm, int wn, int lane) {
    uint32_t abase = s2u(As), bbase = s2u(Bs);
#pragma unroll
    for (int ks = 0; ks < 64; ks += 16) {
        uint32_t a[2][4];
#pragma unroll
        for (int t = 0; t < 2; t++) {
            uint32_t row = wm * 32 + t * 16 + ((lane >> 3) & 1) * 8 + (lane & 7);
            uint32_t cb = (ks + (lane >> 4) * 8) * 2;
            uint32_t ad = abase + swz128(row * 128 + cb);
            asm volatile("ldmatrix.sync.aligned.m8n8.x4.shared.b16 {%0,%1,%2,%3},[%4];"
                         : "=r"(a[t][0]), "=r"(a[t][1]), "=r"(a[t][2]), "=r"(a[t][3])
                         : "r"(ad));
        }
        uint32_t b[8][2];
#pragma unroll
        for (int p4 = 0; p4 < 4; p4++) {
            uint32_t r0, r1, r2, r3;
            if (BT) {
                uint32_t row = ks + ((lane >> 3) & 1) * 8 + (lane & 7);
                uint32_t cb = (wn * 64 + p4 * 16 + (lane >> 4) * 8) * 2;
                uint32_t ad = bbase + swzkn(row, cb);
                asm volatile("ldmatrix.sync.aligned.m8n8.x4.trans.shared.b16 {%0,%1,%2,%3},[%4];"
                             : "=r"(r0), "=r"(r1), "=r"(r2), "=r"(r3) : "r"(ad));
            } else {
                uint32_t row = wn * 64 + p4 * 16 + (lane >> 4) * 8 + (lane & 7);
                uint32_t cb = (ks + ((lane >> 3) & 1) * 8) * 2;
                uint32_t ad = bbase + swz128(row * 128 + cb);
                asm volatile("ldmatrix.sync.aligned.m8n8.x4.shared.b16 {%0,%1,%2,%3},[%4];"
                             : "=r"(r0), "=r"(r1), "=r"(r2), "=r"(r3) : "r"(ad));
            }
            b[2 * p4][0] = r0; b[2 * p4][1] = r1;
            b[2 * p4 + 1][0] = r2; b[2 * p4 + 1][1] = r3;
        }
#pragma unroll
        for (int t = 0; t < 2; t++)
#pragma unroll
            for (int j = 0; j < 8; j++)
                mma_bf16(acc[t * 8 + j], a[t], b[j]);
    }
}

// ---------------- pipelined GEMM kernel ----------------
// MODE 0=scores(+exp+rowsum) 1=hrp(+renorm) 2=mlp(+GLU) 3=conv(+GLU+res)
#define STAGE_BYTES 16384
#define B_SMEM_OFF  (3 * 16384)
#define SMEM_TOTAL  (6 * 16384)

template <int MODE>
__device__ __forceinline__ void load_chunk(char* smem, int s, int k0, int tid,
                                           int bx, int by, int bz, int layer,
                                           const bf16* xsrc) {
    char* Ab = smem + s * STAGE_BYTES;
    char* Bb = smem + B_SMEM_OFF + s * STAGE_BYTES;
    {
        int row = tid >> 1, h = tid & 1;
        const bf16* src; bool v = true;
        if (MODE == 0) {
            src = g_LIS + ((size_t)(bz * LL + by * 128 + row) * TWO_D + k0);
        } else if (MODE == 1) {
            src = g_S + ((size_t)(bz * LL + by * 128 + row) * LL + k0);
        } else if (MODE == 2) {
            int r = by * 128 + row;
            if (k0 < 512)       src = g_LIS + ((size_t)r * TWO_D + k0);
            else if (k0 < 1024) src = g_HRP + ((size_t)r * TWO_D + (k0 - 512));
            else                src = g_cqc + ((size_t)r * DD + (k0 - 1024));
        } else {
            int ls = by * 128 + row + (k0 >> 8) - 3;
            v = (ls >= 0); if (!v) ls = 0;
            src = xsrc + ((size_t)(bz * LL + ls) * DD + (k0 & 255));
        }
#pragma unroll
        for (int j = 0; j < 4; j++) {
            uint32_t cb = h * 64 + j * 16;
            cp16(Ab + swz128((uint32_t)row * 128 + cb), src + cb / 2, v);
        }
    }
    if (MODE == 1) {
        int row = tid >> 2, q = tid & 3;
        const bf16* src = g_LIS + ((size_t)(bz * LL + k0 + row) * TWO_D + bx * 128);
#pragma unroll
        for (int j = 0; j < 4; j++) {
            uint32_t cb = q * 64 + j * 16;
            cp16(Bb + swzkn((uint32_t)row, cb), src + cb / 2, true);
        }
    } else {
        int row = tid >> 1, h = tid & 1;
        const bf16* src;
        if (MODE == 0)      src = g_LIS + ((size_t)(bz * LL + bx * 128 + row) * TWO_D + k0);
        else if (MODE == 2) src = g_WmlpP + ((size_t)(bx * 128 + row) * HD + k0);
        else                src = g_convwP + ((size_t)(layer * TWO_D + bx * 128 + row)) * 1024 + k0;
#pragma unroll
        for (int j = 0; j < 4; j++) {
            uint32_t cb = h * 64 + j * 16;
            cp16(Bb + swz128((uint32_t)row * 128 + cb), src + cb / 2, true);
        }
    }
}

template <int MODE>
__global__ void __launch_bounds__(256, 2) k_gemm(const bf16* __restrict__ xsrc,
                                                 bf16* __restrict__ xdst,
                                                 const float* __restrict__ biasP,
                                                 int layer) {
    extern __shared__ char smem[];
    int tid = threadIdx.x, wid = tid >> 5, lane = tid & 31;
    int bx = blockIdx.x, by = blockIdx.y, bz = blockIdx.z;
    if (MODE == 0 && bx > by) return;
    int nch = (MODE == 0) ? 4 : (MODE == 1) ? (by + 1) * 2 : (MODE == 2) ? 20 : 16;
    int wm = wid >> 1, wn = wid & 1;

    float acc[16][4] = {};

    load_chunk<MODE>(smem, 0, 0, tid, bx, by, bz, layer, xsrc);  CP_COMMIT();
    load_chunk<MODE>(smem, 1, 64, tid, bx, by, bz, layer, xsrc); CP_COMMIT();

#pragma unroll 1
    for (int i = 0; i < nch; i++) {
        int s = i % 3;
        if (i == nch - 1) asm volatile("cp.async.wait_group 0;" ::: "memory");
        else              asm volatile("cp.async.wait_group 1;" ::: "memory");
        __syncthreads();
        if (i + 2 < nch) {
            load_chunk<MODE>(smem, (i + 2) % 3, (i + 2) * 64, tid, bx, by, bz, layer, xsrc);
            CP_COMMIT();
        }
        warp_k64<(MODE == 1)>(smem + s * STAGE_BYTES, smem + B_SMEM_OFF + s * STAGE_BYTES,
                              acc, wm, wn, lane);
    }

    if (MODE == 0) {
        // exp + causal zero + write P; accumulate row sums; record diagonal pii
        bf16* out = g_S + ((size_t)(bz * LL + by * 128)) * LL + bx * 128;
        float* rs = g_rowsum + (size_t)bz * LL;
        float* pii = g_pii + (size_t)bz * LL;
#pragma unroll
        for (int t = 0; t < 2; t++) {
            int r = wm * 32 + t * 16 + (lane >> 2);
            int gi0 = by * 128 + r, gi1 = gi0 + 8;
            float s0 = 0.f, s1 = 0.f;
#pragma unroll
            for (int j = 0; j < 8; j++) {
                int cc = wn * 64 + j * 8 + (lane & 3) * 2;
                int gc = bx * 128 + cc;
                float* a = acc[t * 8 + j];
                float e0 = expp(a[0]), e1 = expp(a[1]);
                float e2 = expp(a[2]), e3 = expp(a[3]);
                if (gc == gi0)     pii[gi0] = e0;
                if (gc + 1 == gi0) pii[gi0] = e1;
                if (gc == gi1)     pii[gi1] = e2;
                if (gc + 1 == gi1) pii[gi1] = e3;
                float p0 = (gc < gi0)     ? e0 : 0.f;
                float p1 = (gc + 1 < gi0) ? e1 : 0.f;
                float p2 = (gc < gi1)     ? e2 : 0.f;
                float p3 = (gc + 1 < gi1) ? e3 : 0.f;
                s0 += p0 + p1; s1 += p2 + p3;
                *(bf162*)(out + (size_t)r * LL + cc)       = __floats2bfloat162_rn(p0, p1);
                *(bf162*)(out + (size_t)(r + 8) * LL + cc) = __floats2bfloat162_rn(p2, p3);
            }
            s0 += __shfl_xor_sync(0xffffffffu, s0, 1);
            s0 += __shfl_xor_sync(0xffffffffu, s0, 2);
            s1 += __shfl_xor_sync(0xffffffffu, s1, 1);
            s1 += __shfl_xor_sync(0xffffffffu, s1, 2);
            if ((lane & 3) == 0) {
                atomicAdd(&rs[gi0], s0);
                atomicAdd(&rs[gi1], s1);
            }
        }
    } else if (MODE == 1) {
        // renormalize rows: inv = 1/(rs + 1e-8*(rs+pii))
        bf16* out = g_HRP + ((size_t)(bz * LL + by * 128)) * TWO_D + bx * 128;
        const float* rs = g_rowsum + (size_t)bz * LL;
        const float* pii = g_pii + (size_t)bz * LL;
#pragma unroll
        for (int t = 0; t < 2; t++) {
            int r = wm * 32 + t * 16 + (lane >> 2);
            int gi0 = by * 128 + r, gi1 = gi0 + 8;
            float r0 = rs[gi0], r1 = rs[gi1];
            float inv0 = 1.f / (r0 + 1e-8f * (r0 + pii[gi0]));
            float inv1 = 1.f / (r1 + 1e-8f * (r1 + pii[gi1]));
#pragma unroll
            for (int j = 0; j < 8; j++) {
                int cc = wn * 64 + j * 8 + (lane & 3) * 2;
                float* a = acc[t * 8 + j];
                *(bf162*)(out + (size_t)r * TWO_D + cc) =
                    __floats2bfloat162_rn(a[0] * inv0, a[1] * inv0);
                *(bf162*)(out + (size_t)(r + 8) * TWO_D + cc) =
                    __floats2bfloat162_rn(a[2] * inv1, a[3] * inv1);
            }
        }
    } else {
        // register-resident GLU epilogue
#pragma unroll
        for (int t = 0; t < 2; t++)
#pragma unroll
            for (int j = 0; j < 4; j++) {
                int r = wm * 32 + t * 16 + (lane >> 2);
                int pc = wn * 64 + j * 8 + (lane & 3) * 2;
                float ba0 = biasP[bx * 128 + pc],      ba1 = biasP[bx * 128 + pc + 1];
                float bg0 = biasP[bx * 128 + pc + 32], bg1 = biasP[bx * 128 + pc + 33];
                float* a = acc[t * 8 + j];
                float* g = acc[t * 8 + j + 4];
                int ocol = (bx * 2 + wn) * 32 + j * 8 + (lane & 3) * 2;
                size_t gr0 = (MODE == 2) ? (size_t)(by * 128 + r)
                                         : ((size_t)bz * LL + by * 128 + r);
                float v0 = (a[0] + ba0) * sigmoidf_(g[0] + bg0);
                float v1 = (a[1] + ba1) * sigmoidf_(g[1] + bg1);
                float v2 = (a[2] + ba0) * sigmoidf_(g[2] + bg0);
                float v3 = (a[3] + ba1) * sigmoidf_(g[3] + bg1);
                if (MODE == 3) {
                    bf162 r0 = *(const bf162*)(xsrc + gr0 * DD + ocol);
                    bf162 r1 = *(const bf162*)(xsrc + (gr0 + 8) * DD + ocol);
                    v0 += __bfloat162float(r0.x); v1 += __bfloat162float(r0.y);
                    v2 += __bfloat162float(r1.x); v3 += __bfloat162float(r1.y);
                }
                *(bf162*)(xdst + gr0 * DD + ocol)       = __floats2bfloat162_rn(v0, v1);
                *(bf162*)(xdst + (gr0 + 8) * DD + ocol) = __floats2bfloat162_rn(v2, v3);
            }
    }
}

// ---------------- merged prep kernel ----------------
// sections: [0] wmlp pack 2560, [1] zero rowsum 256, [2] biasP 2,
//           [3] convwP 768, [4] cqc 16384, [5] embed 65536
#define PB0 2560
#define PB1 (PB0 + 256)
#define PB2 (PB1 + 2)
#define PB3 (PB2 + 768)
#define PB4 (PB3 + 16384)
#define PB5 (PB4 + 65536)

__global__ __launch_bounds__(256) void k_prep(const float* __restrict__ W1w,
                                              const float* __restrict__ W2w,
                                              const float* __restrict__ b1,
                                              const float* __restrict__ b2,
                                              const float* __restrict__ convb,
                                              const float* __restrict__ convw,
                                              const float* __restrict__ cqc,
                                              const int* __restrict__ q,
                                              const int* __restrict__ c,
                                              const float* __restrict__ Eq,
                                              const float* __restrict__ Ec) {
    __shared__ bf16 tile[64][40];
    int bid = blockIdx.x, tid = threadIdx.x;
    if (bid < PB0) {
        int id = bid * 256 + tid;
        if (id < TWO_D * HD) {
            int pn = id / HD, k = id % HD;
            int n = unpackN64(pn);
            float v = (n < DD) ? W1w[(size_t)n * HD + k] : W2w[(size_t)(n - DD) * HD + k];
            g_WmlpP[id] = __float2bfloat16(v);
        }
    } else if (bid < PB1) {
        int id = (bid - PB0) * 256 + tid;
        g_rowsum[id] = 0.f;
    } else if (bid < PB2) {
        int pn = (bid - PB1) * 256 + tid;
        int n = unpackN64(pn);
        g_bP[pn] = (n < DD) ? b1[n] : b2[n - DD];
        for (int l = 0; l < 3; l++)
            g_bconvP[l * TWO_D + pn] = convb[l * TWO_D + n];
    } else if (bid < PB3) {
        int id = bid - PB2;
        int kx = id & 15, ny = (id >> 4) & 15, l = id >> 8;
        int k0 = kx * 64, n0 = ny * 32;
        {
            int row = tid >> 2, seg = tid & 3;
            const float* src = convw + ((size_t)(l * 1024 + k0 + row)) * TWO_D + n0 + seg * 8;
            float4 v0 = *(const float4*)src;
            float4 v1 = *(const float4*)(src + 4);
            tile[row][seg * 8 + 0] = __float2bfloat16(v0.x);
            tile[row][seg * 8 + 1] = __float2bfloat16(v0.y);
            tile[row][seg * 8 + 2] = __float2bfloat16(v0.z);
            tile[row][seg * 8 + 3] = __float2bfloat16(v0.w);
            tile[row][seg * 8 + 4] = __float2bfloat16(v1.x);
            tile[row][seg * 8 + 5] = __float2bfloat16(v1.y);
            tile[row][seg * 8 + 6] = __float2bfloat16(v1.z);
            tile[row][seg * 8 + 7] = __float2bfloat16(v1.w);
        }
        __syncthreads();
        {
            int s = (n0 < 256) ? (n0 >> 5) : ((n0 - 256) >> 5);
            int pn0 = s * 64 + ((n0 < 256) ? 0 : 32);
            int row = tid >> 3, seg = tid & 7;
            bf16 buf[8];
#pragma unroll
            for (int j = 0; j < 8; j++) buf[j] = tile[seg * 8 + j][row];
            bf16* dst = g_convwP + ((size_t)(l * TWO_D + pn0 + row)) * 1024 + k0 + seg * 8;
            *(uint4*)dst = *(uint4*)buf;
        }
    } else if (bid < PB4) {
        size_t id = (size_t)(bid - PB3) * 256 + tid;
        float4 v = ((const float4*)cqc)[id];
        bf162* o = (bf162*)g_cqc;
        o[id * 2] = __floats2bfloat162_rn(v.x, v.y);
        o[id * 2 + 1] = __floats2bfloat162_rn(v.z, v.w);
    } else {
        int r = bid - PB4, d = tid;
        int qi = q[r], ci = c[r];
        g_LIS[(size_t)r * TWO_D + d]      = __float2bfloat16(Eq[(size_t)qi * DD + d]);
        g_LIS[(size_t)r * TWO_D + DD + d] = __float2bfloat16(Ec[(size_t)ci * DD + d]);
    }
}

// ---------------- predict ----------------
__global__ __launch_bounds__(256) void k_predict(const bf16* __restrict__ xf,
                                                 float* __restrict__ out) {
    int warp = threadIdx.x >> 5, lane = threadIdx.x & 31;
    int o = blockIdx.x * 8 + warp;
    if (o >= BB * (LL - 1)) return;
    int b = o / (LL - 1), l = o % (LL - 1);
    const bf16* xr = xf + (size_t)(b * LL + l) * DD;
    const bf16* qr = g_LIS + (size_t)(b * LL + l + 1) * TWO_D;
    float s = 0.f;
    for (int d = lane; d < DD; d += 32)
        s += __bfloat162float(xr[d]) * __bfloat162float(qr[d]);
#pragma unroll
    for (int off = 16; off > 0; off >>= 1) s += __shfl_down_sync(0xffffffffu, s, off);
    if (lane == 0) out[o] = sigmoidf_(s);
}

static bf16* addr_x() { void* p; cudaGetSymbolAddress(&p, g_x); return (bf16*)p; }
static bf16* addr_x2() { void* p; cudaGetSymbolAddress(&p, g_x2); return (bf16*)p; }
static float* addr_bP() { void* p; cudaGetSymbolAddress(&p, g_bP); return (float*)p; }
static float* addr_bconvP() { void* p; cudaGetSymbolAddress(&p, g_bconvP); return (float*)p; }

// ---------------- launch ----------------
extern "C" void kernel_launch(void* const* d_in, const int* in_sizes, int n_in,
                              void* d_out, int out_size) {
    (void)in_sizes; (void)n_in; (void)out_size;
    const int*   q     = (const int*)d_in[0];
    const int*   c     = (const int*)d_in[1];
    const float* cqc   = (const float*)d_in[2];
    const float* Eq    = (const float*)d_in[3];
    const float* Ec    = (const float*)d_in[4];
    const float* W1w   = (const float*)d_in[5];
    const float* W1b   = (const float*)d_in[6];
    const float* W2w   = (const float*)d_in[7];
    const float* W2b   = (const float*)d_in[8];
    const float* convw = (const float*)d_in[9];
    const float* convb = (const float*)d_in[10];
    float* out = (float*)d_out;

    static bf16 *xA = nullptr, *xB = nullptr;
    static float *bP = nullptr, *bconvP = nullptr;
    static bool init_done = false;
    if (!init_done) {
        cudaFuncSetAttribute(k_gemm<0>, cudaFuncAttributeMaxDynamicSharedMemorySize, SMEM_TOTAL);
        cudaFuncSetAttribute(k_gemm<1>, cudaFuncAttributeMaxDynamicSharedMemorySize, SMEM_TOTAL);
        cudaFuncSetAttribute(k_gemm<2>, cudaFuncAttributeMaxDynamicSharedMemorySize, SMEM_TOTAL);
        cudaFuncSetAttribute(k_gemm<3>, cudaFuncAttributeMaxDynamicSharedMemorySize, SMEM_TOTAL);
        xA = addr_x(); xB = addr_x2();
        bP = addr_bP(); bconvP = addr_bconvP();
        init_done = true;
    }

    k_prep<<<PB5, 256>>>(W1w, W2w, W1b, W2b, convb, convw, cqc, q, c, Eq, Ec);

    k_gemm<0><<<dim3(8, 8, BB), 256, SMEM_TOTAL>>>(nullptr, nullptr, nullptr, 0);
    k_gemm<1><<<dim3(4, 8, BB), 256, SMEM_TOTAL>>>(nullptr, nullptr, nullptr, 0);
    k_gemm<2><<<dim3(4, 512, 1), 256, SMEM_TOTAL>>>(nullptr, xA, bP, 0);
    bf16* src = xA;
    bf16* dst = xB;
    for (int l = 0; l < 3; l++) {
        k_gemm<3><<<dim3(4, 8, BB), 256, SMEM_TOTAL>>>(src, dst, bconvP + l * TWO_D, l);
        bf16* t = src; src = dst; dst = t;
    }
    k_predict<<<(BB * (LL - 1) + 7) / 8, 256>>>(src, out);
}

// round 8
// speedup vs baseline: 1.6386x; 1.0014x over previous
#include <cuda_runtime.h>
#include <cuda_bf16.h>
#include <math.h>
#include <stdint.h>

#define BB 64
#define LL 1024
#define DD 256
#define TWO_D 512
#define HD 1280

typedef __nv_bfloat16 bf16;
typedef __nv_bfloat162 bf162;

// ---------------- scratch (device globals) ----------------
__device__ bf16 g_LIS[(size_t)BB * LL * TWO_D];      // [B*L][512] (qe|ce)
__device__ bf16 g_S[(size_t)BB * LL * LL];           // [B][L][L] holds exp'd causal P
__device__ bf16 g_HRP[(size_t)BB * LL * TWO_D];
__device__ bf16 g_x[(size_t)BB * LL * DD];           // ping
__device__ bf16 g_x2[(size_t)BB * LL * DD];          // pong
__device__ bf16 g_cqc[(size_t)BB * LL * DD];
__device__ bf16 g_WmlpP[(size_t)TWO_D * HD];         // packed [pn=512][k=1280]
__device__ float g_bP[TWO_D];                        // packed mlp bias
__device__ bf16 g_convwP[(size_t)3 * TWO_D * 1024];  // packed [l][pn=512][k=1024]
__device__ float g_bconvP[3 * TWO_D];                // packed conv bias
__device__ float g_rowsum[(size_t)BB * LL];          // sum_{j<i} e^{s_ij}
__device__ float g_pii[(size_t)BB * LL];             // e^{s_ii}

__device__ __forceinline__ float sigmoidf_(float v) { return 1.f / (1.f + __expf(-v)); }

__device__ __forceinline__ float expp(float x) {
    float e = fmaf(x, 0.00833333f, 0.04166667f);
    e = fmaf(x, e, 0.16666667f);
    e = fmaf(x, e, 0.5f);
    e = fmaf(x, e, 1.0f);
    e = fmaf(x, e, 1.0f);
    if (fabsf(x) > 0.5f) e = __expf(x);
    return e;
}

// packed col mapping: pn = 64*s + c; c<32 -> a-col s*32+c ; else gate-col 256+s*32+(c-32)
__device__ __forceinline__ int unpackN64(int pn) {
    int s = pn >> 6, c = pn & 63;
    return (c < 32) ? s * 32 + c : 256 + s * 32 + (c - 32);
}

// ---------------- async copy ----------------
__device__ __forceinline__ uint32_t s2u(const void* p) {
    return (uint32_t)__cvta_generic_to_shared(p);
}
__device__ __forceinline__ void cp16(char* dst, const void* src, bool v) {
    asm volatile("cp.async.cg.shared.global [%0], [%1], 16, %2;"
                 :: "r"(s2u(dst)), "l"(src), "r"(v ? 16 : 0));
}
#define CP_COMMIT() asm volatile("cp.async.commit_group;" ::: "memory")

// ---------------- mma ----------------
__device__ __forceinline__ void mma_bf16(float* c, const uint32_t* a, const uint32_t* b) {
    asm volatile(
        "mma.sync.aligned.m16n8k16.row.col.f32.bf16.bf16.f32 "
        "{%0,%1,%2,%3}, {%4,%5,%6,%7}, {%8,%9}, {%0,%1,%2,%3};"
        : "+f"(c[0]), "+f"(c[1]), "+f"(c[2]), "+f"(c[3])
        : "r"(a[0]), "r"(a[1]), "r"(a[2]), "r"(a[3]), "r"(b[0]), "r"(b[1]));
}

// ---------------- swizzles ----------------
__device__ __forceinline__ uint32_t swz128(uint32_t off) {
    return off ^ ((off >> 3) & 0x70);
}
__device__ __forceinline__ uint32_t swzkn(uint32_t row, uint32_t cb) {
    uint32_t unit = (cb >> 4) & 7;
    return row * 256 + (cb & 0x80) + ((unit ^ (row & 7)) << 4) + (cb & 15);
}

// ---------------- fragment loaders ----------------
__device__ __forceinline__ void ldsmA(uint32_t abase, int ks16, int wm, int lane,
                                      uint32_t a[2][4]) {
#pragma unroll
    for (int t = 0; t < 2; t++) {
        uint32_t row = wm * 32 + t * 16 + ((lane >> 3) & 1) * 8 + (lane & 7);
        uint32_t cb = (ks16 * 16 + (lane >> 4) * 8) * 2;
        uint32_t ad = abase + swz128(row * 128 + cb);
        asm volatile("ldmatrix.sync.aligned.m8n8.x4.shared.b16 {%0,%1,%2,%3},[%4];"
                     : "=r"(a[t][0]), "=r"(a[t][1]), "=r"(a[t][2]), "=r"(a[t][3])
                     : "r"(ad));
    }
}

template <bool BT>
__device__ __forceinline__ void ldsmB(uint32_t bbase, int ks16, int h, int wn, int lane,
                                      uint32_t bf[4][2]) {
#pragma unroll
    for (int li = 0; li < 2; li++) {
        int p4 = 2 * h + li;
        uint32_t r0, r1, r2, r3;
        if (BT) {
            uint32_t row = ks16 * 16 + ((lane >> 3) & 1) * 8 + (lane & 7);
            uint32_t cb = (wn * 64 + p4 * 16 + (lane >> 4) * 8) * 2;
            uint32_t ad = bbase + swzkn(row, cb);
            asm volatile("ldmatrix.sync.aligned.m8n8.x4.trans.shared.b16 {%0,%1,%2,%3},[%4];"
                         : "=r"(r0), "=r"(r1), "=r"(r2), "=r"(r3) : "r"(ad));
        } else {
            uint32_t row = wn * 64 + p4 * 16 + (lane >> 4) * 8 + (lane & 7);
            uint32_t cb = (ks16 * 16 + ((lane >> 3) & 1) * 8) * 2;
            uint32_t ad = bbase + swz128(row * 128 + cb);
            asm volatile("ldmatrix.sync.aligned.m8n8.x4.shared.b16 {%0,%1,%2,%3},[%4];"
                         : "=r"(r0), "=r"(r1), "=r"(r2), "=r"(r3) : "r"(ad));
        }
        bf[2 * li][0] = r0; bf[2 * li][1] = r1;
        bf[2 * li + 1][0] = r2; bf[2 * li + 1][1] = r3;
    }
}

// ---------------- software-pipelined K=64 chunk ----------------
// 8 stages: stage st = (ks16 = st>>1, half h = st&1). Each stage: prefetch next
// stage's B (and A at half-0), then 8 MMAs on current double-buffered fragments.
template <bool BT>
__device__ __forceinline__ void warp_k64(const char* As, const char* Bs,
                                         float acc[16][4], int wm, int wn, int lane) {
    uint32_t abase = s2u(As), bbase = s2u(Bs);
    uint32_t a0[2][4], a1[2][4], b0[4][2], b1[4][2];
    ldsmA(abase, 0, wm, lane, a0);
    ldsmB<BT>(bbase, 0, 0, wn, lane, b0);
#pragma unroll
    for (int st = 0; st < 8; st++) {
        int ks = st >> 1, h = st & 1;
        // prefetch next-stage B into the alternate buffer
        if (st + 1 < 8) {
            int nks = (st + 1) >> 1, nh = (st + 1) & 1;
            if (st & 1) ldsmB<BT>(bbase, nks, nh, wn, lane, b0);
            else        ldsmB<BT>(bbase, nks, nh, wn, lane, b1);
        }
        // prefetch next ks's A during the first half
        if (h == 0 && ks < 3) {
            if (ks & 1) ldsmA(abase, ks + 1, wm, lane, a0);
            else        ldsmA(abase, ks + 1, wm, lane, a1);
        }
        uint32_t (*ac)[4] = (ks & 1) ? a1 : a0;
        uint32_t (*bc)[2] = (st & 1) ? b1 : b0;
#pragma unroll
        for (int t = 0; t < 2; t++)
#pragma unroll
            for (int jj = 0; jj < 4; jj++)
                mma_bf16(acc[t * 8 + h * 4 + jj], ac[t], bc[jj]);
    }
}

// ---------------- pipelined GEMM kernel ----------------
// MODE 0=scores(+exp+rowsum) 1=hrp(+renorm) 2=mlp(+GLU) 3=conv(+GLU+res)
#define STAGE_BYTES 16384
#define B_SMEM_OFF  (3 * 16384)
#define SMEM_TOTAL  (6 * 16384)

template <int MODE>
__device__ __forceinline__ void load_chunk(char* smem, int s, int k0, int tid,
                                           int bx, int by, int bz, int layer,
                                           const bf16* xsrc) {
    char* Ab = smem + s * STAGE_BYTES;
    char* Bb = smem + B_SMEM_OFF + s * STAGE_BYTES;
    {
        int row = tid >> 1, h = tid & 1;
        const bf16* src; bool v = true;
        if (MODE == 0) {
            src = g_LIS + ((size_t)(bz * LL + by * 128 + row) * TWO_D + k0);
        } else if (MODE == 1) {
            src = g_S + ((size_t)(bz * LL + by * 128 + row) * LL + k0);
        } else if (MODE == 2) {
            int r = by * 128 + row;
            if (k0 < 512)       src = g_LIS + ((size_t)r * TWO_D + k0);
            else if (k0 < 1024) src = g_HRP + ((size_t)r * TWO_D + (k0 - 512));
            else                src = g_cqc + ((size_t)r * DD + (k0 - 1024));
        } else {
            int ls = by * 128 + row + (k0 >> 8) - 3;
            v = (ls >= 0); if (!v) ls = 0;
            src = xsrc + ((size_t)(bz * LL + ls) * DD + (k0 & 255));
        }
#pragma unroll
        for (int j = 0; j < 4; j++) {
            uint32_t cb = h * 64 + j * 16;
            cp16(Ab + swz128((uint32_t)row * 128 + cb), src + cb / 2, v);
        }
    }
    if (MODE == 1) {
        int row = tid >> 2, q = tid & 3;
        const bf16* src = g_LIS + ((size_t)(bz * LL + k0 + row) * TWO_D + bx * 128);
#pragma unroll
        for (int j = 0; j < 4; j++) {
            uint32_t cb = q * 64 + j * 16;
            cp16(Bb + swzkn((uint32_t)row, cb), src + cb / 2, true);
        }
    } else {
        int row = tid >> 1, h = tid & 1;
        const bf16* src;
        if (MODE == 0)      src = g_LIS + ((size_t)(bz * LL + bx * 128 + row) * TWO_D + k0);
        else if (MODE == 2) src = g_WmlpP + ((size_t)(bx * 128 + row) * HD + k0);
        else                src = g_convwP + ((size_t)(layer * TWO_D + bx * 128 + row)) * 1024 + k0;
#pragma unroll
        for (int j = 0; j < 4; j++) {
            uint32_t cb = h * 64 + j * 16;
            cp16(Bb + swz128((uint32_t)row * 128 + cb), src + cb / 2, true);
        }
    }
}

template <int MODE>
__global__ void __launch_bounds__(256, 2) k_gemm(const bf16* __restrict__ xsrc,
                                                 bf16* __restrict__ xdst,
                                                 const float* __restrict__ biasP,
                                                 int layer) {
    extern __shared__ char smem[];
    int tid = threadIdx.x, wid = tid >> 5, lane = tid & 31;
    int bx = blockIdx.x, by = blockIdx.y, bz = blockIdx.z;
    if (MODE == 0 && bx > by) return;
    int nch = (MODE == 0) ? 4 : (MODE == 1) ? (by + 1) * 2 : (MODE == 2) ? 20 : 16;
    int wm = wid >> 1, wn = wid & 1;

    float acc[16][4] = {};

    load_chunk<MODE>(smem, 0, 0, tid, bx, by, bz, layer, xsrc);  CP_COMMIT();
    load_chunk<MODE>(smem, 1, 64, tid, bx, by, bz, layer, xsrc); CP_COMMIT();

#pragma unroll 1
    for (int i = 0; i < nch; i++) {
        int s = i % 3;
        if (i == nch - 1) asm volatile("cp.async.wait_group 0;" ::: "memory");
        else              asm volatile("cp.async.wait_group 1;" ::: "memory");
        __syncthreads();
        if (i + 2 < nch) {
            load_chunk<MODE>(smem, (i + 2) % 3, (i + 2) * 64, tid, bx, by, bz, layer, xsrc);
            CP_COMMIT();
        }
        warp_k64<(MODE == 1)>(smem + s * STAGE_BYTES, smem + B_SMEM_OFF + s * STAGE_BYTES,
                              acc, wm, wn, lane);
    }

    if (MODE == 0) {
        bf16* out = g_S + ((size_t)(bz * LL + by * 128)) * LL + bx * 128;
        float* rs = g_rowsum + (size_t)bz * LL;
        float* pii = g_pii + (size_t)bz * LL;
#pragma unroll
        for (int t = 0; t < 2; t++) {
            int r = wm * 32 + t * 16 + (lane >> 2);
            int gi0 = by * 128 + r, gi1 = gi0 + 8;
            float s0 = 0.f, s1 = 0.f;
#pragma unroll
            for (int j = 0; j < 8; j++) {
                int cc = wn * 64 + j * 8 + (lane & 3) * 2;
                int gc = bx * 128 + cc;
                float* a = acc[t * 8 + j];
                float e0 = expp(a[0]), e1 = expp(a[1]);
                float e2 = expp(a[2]), e3 = expp(a[3]);
                if (gc == gi0)     pii[gi0] = e0;
                if (gc + 1 == gi0) pii[gi0] = e1;
                if (gc == gi1)     pii[gi1] = e2;
                if (gc + 1 == gi1) pii[gi1] = e3;
                float p0 = (gc < gi0)     ? e0 : 0.f;
                float p1 = (gc + 1 < gi0) ? e1 : 0.f;
                float p2 = (gc < gi1)     ? e2 : 0.f;
                float p3 = (gc + 1 < gi1) ? e3 : 0.f;
                s0 += p0 + p1; s1 += p2 + p3;
                *(bf162*)(out + (size_t)r * LL + cc)       = __floats2bfloat162_rn(p0, p1);
                *(bf162*)(out + (size_t)(r + 8) * LL + cc) = __floats2bfloat162_rn(p2, p3);
            }
            s0 += __shfl_xor_sync(0xffffffffu, s0, 1);
            s0 += __shfl_xor_sync(0xffffffffu, s0, 2);
            s1 += __shfl_xor_sync(0xffffffffu, s1, 1);
            s1 += __shfl_xor_sync(0xffffffffu, s1, 2);
            if ((lane & 3) == 0) {
                atomicAdd(&rs[gi0], s0);
                atomicAdd(&rs[gi1], s1);
            }
        }
    } else if (MODE == 1) {
        bf16* out = g_HRP + ((size_t)(bz * LL + by * 128)) * TWO_D + bx * 128;
        const float* rs = g_rowsum + (size_t)bz * LL;
        const float* pii = g_pii + (size_t)bz * LL;
#pragma unroll
        for (int t = 0; t < 2; t++) {
            int r = wm * 32 + t * 16 + (lane >> 2);
            int gi0 = by * 128 + r, gi1 = gi0 + 8;
            float r0 = rs[gi0], r1 = rs[gi1];
            float inv0 = 1.f / (r0 + 1e-8f * (r0 + pii[gi0]));
            float inv1 = 1.f / (r1 + 1e-8f * (r1 + pii[gi1]));
#pragma unroll
            for (int j = 0; j < 8; j++) {
                int cc = wn * 64 + j * 8 + (lane & 3) * 2;
                float* a = acc[t * 8 + j];
                *(bf162*)(out + (size_t)r * TWO_D + cc) =
                    __floats2bfloat162_rn(a[0] * inv0, a[1] * inv0);
                *(bf162*)(out + (size_t)(r + 8) * TWO_D + cc) =
                    __floats2bfloat162_rn(a[2] * inv1, a[3] * inv1);
            }
        }
    } else {
#pragma unroll
        for (int t = 0; t < 2; t++)
#pragma unroll
            for (int j = 0; j < 4; j++) {
                int r = wm * 32 + t * 16 + (lane >> 2);
                int pc = wn * 64 + j * 8 + (lane & 3) * 2;
                float ba0 = biasP[bx * 128 + pc],      ba1 = biasP[bx * 128 + pc + 1];
                float bg0 = biasP[bx * 128 + pc + 32], bg1 = biasP[bx * 128 + pc + 33];
                float* a = acc[t * 8 + j];
                float* g = acc[t * 8 + j + 4];
                int ocol = (bx * 2 + wn) * 32 + j * 8 + (lane & 3) * 2;
                size_t gr0 = (MODE == 2) ? (size_t)(by * 128 + r)
                                         : ((size_t)bz * LL + by * 128 + r);
                float v0 = (a[0] + ba0) * sigmoidf_(g[0] + bg0);
                float v1 = (a[1] + ba1) * sigmoidf_(g[1] + bg1);
                float v2 = (a[2] + ba0) * sigmoidf_(g[2] + bg0);
                float v3 = (a[3] + ba1) * sigmoidf_(g[3] + bg1);
                if (MODE == 3) {
                    bf162 r0 = *(const bf162*)(xsrc + gr0 * DD + ocol);
                    bf162 r1 = *(const bf162*)(xsrc + (gr0 + 8) * DD + ocol);
                    v0 += __bfloat162float(r0.x); v1 += __bfloat162float(r0.y);
                    v2 += __bfloat162float(r1.x); v3 += __bfloat162float(r1.y);
                }
                *(bf162*)(xdst + gr0 * DD + ocol)       = __floats2bfloat162_rn(v0, v1);
                *(bf162*)(xdst + (gr0 + 8) * DD + ocol) = __floats2bfloat162_rn(v2, v3);
            }
    }
}

// ---------------- merged prep kernel ----------------
#define PB0 2560
#define PB1 (PB0 + 256)
#define PB2 (PB1 + 2)
#define PB3 (PB2 + 768)
#define PB4 (PB3 + 16384)
#define PB5 (PB4 + 65536)

__global__ __launch_bounds__(256) void k_prep(const float* __restrict__ W1w,
                                              const float* __restrict__ W2w,
                                              const float* __restrict__ b1,
                                              const float* __restrict__ b2,
                                              const float* __restrict__ convb,
                                              const float* __restrict__ convw,
                                              const float* __restrict__ cqc,
                                              const int* __restrict__ q,
                                              const int* __restrict__ c,
                                              const float* __restrict__ Eq,
                                              const float* __restrict__ Ec) {
    __shared__ bf16 tile[64][40];
    int bid = blockIdx.x, tid = threadIdx.x;
    if (bid < PB0) {
        int id = bid * 256 + tid;
        if (id < TWO_D * HD) {
            int pn = id / HD, k = id % HD;
            int n = unpackN64(pn);
            float v = (n < DD) ? W1w[(size_t)n * HD + k] : W2w[(size_t)(n - DD) * HD + k];
            g_WmlpP[id] = __float2bfloat16(v);
        }
    } else if (bid < PB1) {
        int id = (bid - PB0) * 256 + tid;
        g_rowsum[id] = 0.f;
    } else if (bid < PB2) {
        int pn = (bid - PB1) * 256 + tid;
        int n = unpackN64(pn);
        g_bP[pn] = (n < DD) ? b1[n] : b2[n - DD];
        for (int l = 0; l < 3; l++)
            g_bconvP[l * TWO_D + pn] = convb[l * TWO_D + n];
    } else if (bid < PB3) {
        int id = bid - PB2;
        int kx = id & 15, ny = (id >> 4) & 15, l = id >> 8;
        int k0 = kx * 64, n0 = ny * 32;
        {
            int row = tid >> 2, seg = tid & 3;
            const float* src = convw + ((size_t)(l * 1024 + k0 + row)) * TWO_D + n0 + seg * 8;
            float4 v0 = *(const float4*)src;
            float4 v1 = *(const float4*)(src + 4);
            tile[row][seg * 8 + 0] = __float2bfloat16(v0.x);
            tile[row][seg * 8 + 1] = __float2bfloat16(v0.y);
            tile[row][seg * 8 + 2] = __float2bfloat16(v0.z);
            tile[row][seg * 8 + 3] = __float2bfloat16(v0.w);
            tile[row][seg * 8 + 4] = __float2bfloat16(v1.x);
            tile[row][seg * 8 + 5] = __float2bfloat16(v1.y);
            tile[row][seg * 8 + 6] = __float2bfloat16(v1.z);
            tile[row][seg * 8 + 7] = __float2bfloat16(v1.w);
        }
        __syncthreads();
        {
            int s = (n0 < 256) ? (n0 >> 5) : ((n0 - 256) >> 5);
            int pn0 = s * 64 + ((n0 < 256) ? 0 : 32);
            int row = tid >> 3, seg = tid & 7;
            bf16 buf[8];
#pragma unroll
            for (int j = 0; j < 8; j++) buf[j] = tile[seg * 8 + j][row];
            bf16* dst = g_convwP + ((size_t)(l * TWO_D + pn0 + row)) * 1024 + k0 + seg * 8;
            *(uint4*)dst = *(uint4*)buf;
        }
    } else if (bid < PB4) {
        size_t id = (size_t)(bid - PB3) * 256 + tid;
        float4 v = ((const float4*)cqc)[id];
        bf162* o = (bf162*)g_cqc;
        o[id * 2] = __floats2bfloat162_rn(v.x, v.y);
        o[id * 2 + 1] = __floats2bfloat162_rn(v.z, v.w);
    } else {
        int r = bid - PB4, d = tid;
        int qi = q[r], ci = c[r];
        g_LIS[(size_t)r * TWO_D + d]      = __float2bfloat16(Eq[(size_t)qi * DD + d]);
        g_LIS[(size_t)r * TWO_D + DD + d] = __float2bfloat16(Ec[(size_t)ci * DD + d]);
    }
}

// ---------------- predict ----------------
__global__ __launch_bounds__(256) void k_predict(const bf16* __restrict__ xf,
                                                 float* __restrict__ out) {
    int warp = threadIdx.x >> 5, lane = threadIdx.x & 31;
    int o = blockIdx.x * 8 + warp;
    if (o >= BB * (LL - 1)) return;
    int b = o / (LL - 1), l = o % (LL - 1);
    const bf16* xr = xf + (size_t)(b * LL + l) * DD;
    const bf16* qr = g_LIS + (size_t)(b * LL + l + 1) * TWO_D;
    float s = 0.f;
    for (int d = lane; d < DD; d += 32)
        s += __bfloat162float(xr[d]) * __bfloat162float(qr[d]);
#pragma unroll
    for (int off = 16; off > 0; off >>= 1) s += __shfl_down_sync(0xffffffffu, s, off);
    if (lane == 0) out[o] = sigmoidf_(s);
}

static bf16* addr_x() { void* p; cudaGetSymbolAddress(&p, g_x); return (bf16*)p; }
static bf16* addr_x2() { void* p; cudaGetSymbolAddress(&p, g_x2); return (bf16*)p; }
static float* addr_bP() { void* p; cudaGetSymbolAddress(&p, g_bP); return (float*)p; }
static float* addr_bconvP() { void* p; cudaGetSymbolAddress(&p, g_bconvP); return (float*)p; }

// ---------------- launch ----------------
extern "C" void kernel_launch(void* const* d_in, const int* in_sizes, int n_in,
                              void* d_out, int out_size) {
    (void)in_sizes; (void)n_in; (void)out_size;
    const int*   q     = (const int*)d_in[0];
    const int*   c     = (const int*)d_in[1];
    const float* cqc   = (const float*)d_in[2];
    const float* Eq    = (const float*)d_in[3];
    const float* Ec    = (const float*)d_in[4];
    const float* W1w   = (const float*)d_in[5];
    const float* W1b   = (const float*)d_in[6];
    const float* W2w   = (const float*)d_in[7];
    const float* W2b   = (const float*)d_in[8];
    const float* convw = (const float*)d_in[9];
    const float* convb = (const float*)d_in[10];
    float* out = (float*)d_out;

    static bf16 *xA = nullptr, *xB = nullptr;
    static float *bP = nullptr, *bconvP = nullptr;
    static bool init_done = false;
    if (!init_done) {
        cudaFuncSetAttribute(k_gemm<0>, cudaFuncAttributeMaxDynamicSharedMemorySize, SMEM_TOTAL);
        cudaFuncSetAttribute(k_gemm<1>, cudaFuncAttributeMaxDynamicSharedMemorySize, SMEM_TOTAL);
        cudaFuncSetAttribute(k_gemm<2>, cudaFuncAttributeMaxDynamicSharedMemorySize, SMEM_TOTAL);
        cudaFuncSetAttribute(k_gemm<3>, cudaFuncAttributeMaxDynamicSharedMemorySize, SMEM_TOTAL);
        xA = addr_x(); xB = addr_x2();
        bP = addr_bP(); bconvP = addr_bconvP();
        init_done = true;
    }

    k_prep<<<PB5, 256>>>(W1w, W2w, W1b, W2b, convb, convw, cqc, q, c, Eq, Ec);

    k_gemm<0><<<dim3(8, 8, BB), 256, SMEM_TOTAL>>>(nullptr, nullptr, nullptr, 0);
    k_gemm<1><<<dim3(4, 8, BB), 256, SMEM_TOTAL>>>(nullptr, nullptr, nullptr, 0);
    k_gemm<2><<<dim3(4, 512, 1), 256, SMEM_TOTAL>>>(nullptr, xA, bP, 0);
    bf16* src = xA;
    bf16* dst = xB;
    for (int l = 0; l < 3; l++) {
        k_gemm<3><<<dim3(4, 8, BB), 256, SMEM_TOTAL>>>(src, dst, bconvP + l * TWO_D, l);
        bf16* t = src; src = dst; dst = t;
    }
    k_predict<<<(BB * (LL - 1) + 7) / 8, 256>>>(src, out);
}